// round 7
// baseline (speedup 1.0000x reference)
#include <cuda_runtime.h>
#include <cstdint>

#define BATCH 8
#define MDIM  2048
#define LDIM  2048
#define HDIM  1024
#define BK    16

// Scratch (module-load allocated; runtime allocs forbidden)
__device__ float g_T [(size_t)BATCH * HDIM * HDIM];  // T = K^T V   [B,H,H]
__device__ float g_Qt[(size_t)BATCH * HDIM * MDIM];  // Q^T         [B,H,M]

// ---------------------------------------------------------------------------
// helpers
// ---------------------------------------------------------------------------
__device__ __forceinline__ uint32_t smem_u32(const void* p) {
    uint32_t a;
    asm("{ .reg .u64 t; cvta.to.shared.u64 t, %1; cvt.u32.u64 %0, t; }"
        : "=r"(a) : "l"(p));
    return a;
}
__device__ __forceinline__ void cp16(uint32_t dst, const void* src) {
    asm volatile("cp.async.cg.shared.global [%0], [%1], 16;"
                 :: "r"(dst), "l"(src) : "memory");
}
__device__ __forceinline__ void cp_commit() {
    asm volatile("cp.async.commit_group;" ::: "memory");
}
__device__ __forceinline__ void cp_wait1() {
    asm volatile("cp.async.wait_group 1;" ::: "memory");
}
__device__ __forceinline__ void cp_wait0() {
    asm volatile("cp.async.wait_group 0;" ::: "memory");
}

// ---------------------------------------------------------------------------
// Generic k-major GEMM: C[m][n] = sum_k A[k][m] * B[k][n]
// A rows k-major (lda), B rows k-major (ldb). 128x128 tile, BK=16,
// 256 threads, 8x8 scalar-FFMA micro-tile, 3-stage cp.async pipeline.
// ---------------------------------------------------------------------------
__global__ __launch_bounds__(256, 2) void sgemm_tn(
    const float* __restrict__ Ap, int lda, size_t bsA,
    const float* __restrict__ Bp, int ldb, size_t bsB,
    float* __restrict__ Cp, int ldc, size_t bsC,
    int Kdim)
{
    extern __shared__ __align__(16) float sm[];
    const uint32_t tb = smem_u32(sm);

    const int tid = threadIdx.x;
    const int ty = tid >> 4, tx = tid & 15;
    const int b = blockIdx.z;
    const int m0 = blockIdx.y * 128, n0 = blockIdx.x * 128;

    const float* A = Ap + (size_t)b * bsA;
    const float* B = Bp + (size_t)b * bsB;

    float acc[8][8];
#pragma unroll
    for (int i = 0; i < 8; i++)
#pragma unroll
        for (int j = 0; j < 8; j++) acc[i][j] = 0.0f;

    // per-chunk async load: 16 rows x 128 floats per matrix = 512 x 16B,
    // 2 segments per thread per matrix.
    auto issue = [&](int it) {
        const uint32_t s = tb + (uint32_t)(it % 3) * 16384u;
        const int k0 = it * BK;
#pragma unroll
        for (int h = 0; h < 2; h++) {
            const int seg = tid + h * 256;          // 0..511
            const int row = seg >> 5;               // 0..15
            const int c4  = seg & 31;               // float4 within row
            const uint32_t off = (uint32_t)(row * 512 + c4 * 16);
            cp16(s + off,         A + (size_t)(k0 + row) * lda + m0 + c4 * 4);
            cp16(s + 8192u + off, B + (size_t)(k0 + row) * ldb + n0 + c4 * 4);
        }
        cp_commit();
    };

    const int NK = Kdim / BK;
    issue(0);
    issue(1);

    for (int c = 0; c < NK; c++) {
        if (c + 2 < NK) cp_wait1(); else cp_wait0();
        __syncthreads();
        if (c + 2 < NK) issue(c + 2);

        const float* As = sm + (size_t)(c % 3) * 4096;  // floats
        const float* Bs = As + 2048;

#pragma unroll
        for (int k = 0; k < BK; k++) {
            float4 a0 = *(const float4*)(As + k * 128 + ty * 8);
            float4 a1 = *(const float4*)(As + k * 128 + ty * 8 + 4);
            float4 b0 = *(const float4*)(Bs + k * 128 + tx * 8);
            float4 b1 = *(const float4*)(Bs + k * 128 + tx * 8 + 4);
            const float av[8] = {a0.x, a0.y, a0.z, a0.w, a1.x, a1.y, a1.z, a1.w};
            const float bv[8] = {b0.x, b0.y, b0.z, b0.w, b1.x, b1.y, b1.z, b1.w};
#pragma unroll
            for (int i = 0; i < 8; i++)
#pragma unroll
                for (int j = 0; j < 8; j++)
                    acc[i][j] = fmaf(av[i], bv[j], acc[i][j]);
        }
    }

    // epilogue: two float4 stores per micro-row
#pragma unroll
    for (int i = 0; i < 8; i++) {
        float* crow = Cp + (size_t)b * bsC + (size_t)(m0 + ty * 8 + i) * ldc + n0 + tx * 8;
        *reinterpret_cast<float4*>(crow) =
            make_float4(acc[i][0], acc[i][1], acc[i][2], acc[i][3]);
        *reinterpret_cast<float4*>(crow + 4) =
            make_float4(acc[i][4], acc[i][5], acc[i][6], acc[i][7]);
    }
}

// ---------------------------------------------------------------------------
// Q transpose: [B,M,H] -> [B,H,M]  (32x32 smem tiles)
// ---------------------------------------------------------------------------
__global__ __launch_bounds__(256) void transpose_q(const float* __restrict__ in,
                                                   float* __restrict__ out)
{
    __shared__ float t[32][33];
    const int b = blockIdx.z;
    const int h0 = blockIdx.x * 32, m0 = blockIdx.y * 32;
    const int tx = threadIdx.x, ty = threadIdx.y;  // (32, 8)

    const float* src = in + (size_t)b * MDIM * HDIM;
#pragma unroll
    for (int k = 0; k < 4; k++)
        t[ty + k * 8][tx] = src[(size_t)(m0 + ty + k * 8) * HDIM + h0 + tx];
    __syncthreads();

    float* dst = out + (size_t)b * HDIM * MDIM;
#pragma unroll
    for (int k = 0; k < 4; k++)
        dst[(size_t)(h0 + ty + k * 8) * MDIM + m0 + tx] = t[tx][ty + k * 8];
}

// ---------------------------------------------------------------------------
// Launch: out = Q @ (K^T @ V). key_pe / hidden_size are dead inputs
// (attn_pos and the softmax are dead code in the reference).
// ---------------------------------------------------------------------------
#define GEMM_SMEM 49152

extern "C" void kernel_launch(void* const* d_in, const int* in_sizes, int n_in,
                              void* d_out, int out_size)
{
    const float* q = (const float*)d_in[0];  // [B, M, H]
    const float* k = (const float*)d_in[1];  // [B, L, H]
    const float* v = (const float*)d_in[2];  // [B, L, H]
    float* out = (float*)d_out;              // [B, M, H]

    cudaFuncSetAttribute(sgemm_tn, cudaFuncAttributeMaxDynamicSharedMemorySize,
                         GEMM_SMEM);

    // 0) Q^T so stage-2 A-tiles are k-major contiguous
    {
        dim3 g(HDIM / 32, MDIM / 32, BATCH), tB(32, 8);
        transpose_q<<<g, tB>>>(q, g_Qt);
    }

    // 1) T[i][j] = sum_l K[l][i] V[l][j]   (A=K rows l, B=V rows l)
    {
        dim3 g1(HDIM / 128, HDIM / 128, BATCH);
        sgemm_tn<<<g1, 256, GEMM_SMEM>>>(
            k, HDIM, (size_t)LDIM * HDIM,
            v, HDIM, (size_t)LDIM * HDIM,
            g_T, HDIM, (size_t)HDIM * HDIM,
            LDIM);
    }

    // 2) O[m][j] = sum_h Qt[h][m] T[h][j]  (A=Qt rows h, B=T rows h)
    {
        dim3 g2(HDIM / 128, MDIM / 128, BATCH);
        sgemm_tn<<<g2, 256, GEMM_SMEM>>>(
            g_Qt, MDIM, (size_t)HDIM * MDIM,
            g_T, HDIM, (size_t)HDIM * HDIM,
            out, HDIM, (size_t)MDIM * HDIM,
            HDIM);
    }
}

// round 8
// speedup vs baseline: 3.7113x; 3.7113x over previous
#include <cuda_runtime.h>
#include <cstdint>

#define BATCH 8
#define MDIM  2048
#define LDIM  2048
#define HDIM  1024
#define BK    16
#define AST   132   /* padded smem row stride (floats) */

// Scratch: T = K^T V, [B,H,H] fp32 (module-load allocated; allocs forbidden)
__device__ float g_T[(size_t)BATCH * HDIM * HDIM];

// ---------------------------------------------------------------------------
// Generic GEMM: C[m][n] = sum_k A'[k][m] * B[k][n]
//   ATRANS=0: A given k-major  [k][m] rows (lda = row stride)   -> direct STS
//   ATRANS=1: A given m-major  [m][k] rows (lda = row stride)   -> transpose STS
//   B always k-major [k][n].
// 128x128 tile, BK=16, 256 threads, 8x8 microtile as split float4s
// (rows ty*4 / 64+ty*4, cols tx*4 / 64+tx*4  -> conflict-free LDS),
// register-staged global prefetch (no cp.async -- measured pathological).
// ---------------------------------------------------------------------------
template <int ATRANS>
__global__ __launch_bounds__(256, 2) void sgemm(
    const float* __restrict__ Ap, int lda, size_t bsA,
    const float* __restrict__ Bp, int ldb, size_t bsB,
    float* __restrict__ Cp, int ldc, size_t bsC,
    int Kdim)
{
    __shared__ float As[BK][AST];
    __shared__ float Bs[BK][AST];

    const int tid = threadIdx.x;
    const int ty = tid >> 4, tx = tid & 15;
    const int b = blockIdx.z;
    const int m0 = blockIdx.y * 128, n0 = blockIdx.x * 128;

    const float* A = Ap + (size_t)b * bsA;
    const float* B = Bp + (size_t)b * bsB;

    // ---- load index precompute (2 float4 per thread per matrix) ----
    // B (and A when k-major): idx = tid + h*256 ; krow = idx>>5 ; c4 = idx&31
    int bk_[2], bc_[2];
#pragma unroll
    for (int h = 0; h < 2; h++) {
        int idx = tid + h * 256;
        bk_[h] = idx >> 5;
        bc_[h] = (idx & 31) << 2;
    }
    // A when m-major: idx = tid + h*256 ; mrow = idx>>2 ; k4 = idx&3
    int am_[2], ak_[2];
#pragma unroll
    for (int h = 0; h < 2; h++) {
        int idx = tid + h * 256;
        am_[h] = idx >> 2;
        ak_[h] = (idx & 3) << 2;
    }

    float4 ra[2], rb[2];
    auto ldg_stage = [&](int k0) {
#pragma unroll
        for (int h = 0; h < 2; h++) {
            if (ATRANS)
                ra[h] = *(const float4*)(A + (size_t)(m0 + am_[h]) * lda + k0 + ak_[h]);
            else
                ra[h] = *(const float4*)(A + (size_t)(k0 + bk_[h]) * lda + m0 + bc_[h]);
            rb[h] = *(const float4*)(B + (size_t)(k0 + bk_[h]) * ldb + n0 + bc_[h]);
        }
    };
    auto sts_stage = [&]() {
#pragma unroll
        for (int h = 0; h < 2; h++) {
            if (ATRANS) {
                As[ak_[h] + 0][am_[h]] = ra[h].x;
                As[ak_[h] + 1][am_[h]] = ra[h].y;
                As[ak_[h] + 2][am_[h]] = ra[h].z;
                As[ak_[h] + 3][am_[h]] = ra[h].w;
            } else {
                *(float4*)&As[bk_[h]][bc_[h]] = ra[h];
            }
            *(float4*)&Bs[bk_[h]][bc_[h]] = rb[h];
        }
    };

    float acc[8][8];
#pragma unroll
    for (int i = 0; i < 8; i++)
#pragma unroll
        for (int j = 0; j < 8; j++) acc[i][j] = 0.0f;

    const int NK = Kdim / BK;
    ldg_stage(0);

    for (int c = 0; c < NK; c++) {
        __syncthreads();           // previous compute done -> safe to overwrite
        sts_stage();
        __syncthreads();           // tiles visible
        if (c + 1 < NK) ldg_stage((c + 1) * BK);   // prefetch overlaps compute

#pragma unroll
        for (int k = 0; k < BK; k++) {
            float4 a0 = *(const float4*)&As[k][ty * 4];
            float4 a1 = *(const float4*)&As[k][64 + ty * 4];
            float4 b0 = *(const float4*)&Bs[k][tx * 4];
            float4 b1 = *(const float4*)&Bs[k][64 + tx * 4];
            const float av[8] = {a0.x, a0.y, a0.z, a0.w, a1.x, a1.y, a1.z, a1.w};
            const float bv[8] = {b0.x, b0.y, b0.z, b0.w, b1.x, b1.y, b1.z, b1.w};
#pragma unroll
            for (int i = 0; i < 8; i++)
#pragma unroll
                for (int j = 0; j < 8; j++)
                    acc[i][j] = fmaf(av[i], bv[j], acc[i][j]);
        }
    }

    // ---- epilogue: rows {m0+ty*4+i, m0+64+ty*4+i}, cols {n0+tx*4, n0+64+tx*4}
#pragma unroll
    for (int i = 0; i < 8; i++) {
        const int gr = m0 + ((i < 4) ? (ty * 4 + i) : (64 + ty * 4 + (i - 4)));
        float* crow = Cp + (size_t)b * bsC + (size_t)gr * ldc + n0;
        *reinterpret_cast<float4*>(crow + tx * 4) =
            make_float4(acc[i][0], acc[i][1], acc[i][2], acc[i][3]);
        *reinterpret_cast<float4*>(crow + 64 + tx * 4) =
            make_float4(acc[i][4], acc[i][5], acc[i][6], acc[i][7]);
    }
}

// ---------------------------------------------------------------------------
// Launch: out = Q @ (K^T @ V). key_pe / hidden_size are dead inputs
// (attn_pos and the softmax are dead code in the reference).
// ---------------------------------------------------------------------------
extern "C" void kernel_launch(void* const* d_in, const int* in_sizes, int n_in,
                              void* d_out, int out_size)
{
    const float* q = (const float*)d_in[0];  // [B, M, H]
    const float* k = (const float*)d_in[1];  // [B, L, H]
    const float* v = (const float*)d_in[2];  // [B, L, H]
    float* out = (float*)d_out;              // [B, M, H]

    // 1) T[i][j] = sum_l K[l][i] V[l][j]   (A = K k-major, B = V k-major)
    {
        dim3 g1(HDIM / 128, HDIM / 128, BATCH);
        sgemm<0><<<g1, 256>>>(
            k, HDIM, (size_t)LDIM * HDIM,
            v, HDIM, (size_t)LDIM * HDIM,
            g_T, HDIM, (size_t)HDIM * HDIM,
            LDIM);
    }

    // 2) O[m][j] = sum_h Q[m][h] T[h][j]   (A = Q m-major, B = T k-major)
    {
        dim3 g2(HDIM / 128, MDIM / 128, BATCH);
        sgemm<1><<<g2, 256>>>(
            q, HDIM, (size_t)MDIM * HDIM,
            g_T, HDIM, (size_t)HDIM * HDIM,
            out, HDIM, (size_t)MDIM * HDIM,
            HDIM);
    }
}

// round 13
// speedup vs baseline: 3.7324x; 1.0057x over previous
#include <cuda_runtime.h>
#include <cstdint>

#define BATCH 8
#define MDIM  2048
#define LDIM  2048
#define HDIM  1024
#define BK    32

// Scratch: T = K^T V, [B,H,H] fp32 (module-load allocated; allocs forbidden)
__device__ float g_T[(size_t)BATCH * HDIM * HDIM];

// ---------------------------------------------------------------------------
// Generic GEMM: C[m][n] = sum_k A'[k][m] * B[k][n]
//   ATRANS=0: A rows k-major [k][m]  -> direct float4 STS
//   ATRANS=1: A rows m-major [m][k]  -> transpose-on-STS (scalar, 2-way ok)
//   B always k-major [k][n].
// 128x128 tile, BK=32, 256 threads, 8x8 microtile:
//   rows  m0 + ty*8 + i        (A broadcast loads)
//   cols  n0 + tx*4 + j  and  n0 + 64 + tx*4 + j   (conflict-free B loads)
// Inline LDG->STS per chunk (transient regs only -- no state lives across
// the FFMA loop; that spilled in R8). No cp.async (measured pathological).
// ---------------------------------------------------------------------------
template <int ATRANS>
__global__ __launch_bounds__(256, 2) void sgemm(
    const float* __restrict__ Ap, int lda, size_t bsA,
    const float* __restrict__ Bp, int ldb, size_t bsB,
    float* __restrict__ Cp, int ldc, size_t bsC,
    int Kdim)
{
    __shared__ float As[BK][128];
    __shared__ float Bs[BK][128];

    const int tid = threadIdx.x;
    const int ty = tid >> 4, tx = tid & 15;
    const int b = blockIdx.z;
    const int m0 = blockIdx.y * 128, n0 = blockIdx.x * 128;

    const float* A = Ap + (size_t)b * bsA;
    const float* B = Bp + (size_t)b * bsB;

    float acc[8][8];
#pragma unroll
    for (int i = 0; i < 8; i++)
#pragma unroll
        for (int j = 0; j < 8; j++) acc[i][j] = 0.0f;

    const int NK = Kdim / BK;

    for (int c = 0; c < NK; c++) {
        const int k0 = c * BK;

        // ---- load chunk: 4 float4 per thread per matrix (transient regs) ----
        float4 ra[4], rb[4];
#pragma unroll
        for (int h = 0; h < 4; h++) {
            const int idx = tid + h * 256;
            const int kr = idx >> 5;             // 0..31
            const int c4 = (idx & 31) << 2;      // 0..124
            if (ATRANS) {
                const int am = tid >> 1, akk = (tid & 1) << 2;
                ra[h] = *(const float4*)(A + (size_t)(m0 + am) * lda + k0 + h * 8 + akk);
            } else {
                ra[h] = *(const float4*)(A + (size_t)(k0 + kr) * lda + m0 + c4);
            }
            rb[h] = *(const float4*)(B + (size_t)(k0 + kr) * ldb + n0 + c4);
        }
        __syncthreads();   // previous compute done -> safe to overwrite tiles
#pragma unroll
        for (int h = 0; h < 4; h++) {
            const int idx = tid + h * 256;
            const int kr = idx >> 5;
            const int c4 = (idx & 31) << 2;
            if (ATRANS) {
                const int am = tid >> 1, akk = (tid & 1) << 2;
                As[h * 8 + akk + 0][am] = ra[h].x;
                As[h * 8 + akk + 1][am] = ra[h].y;
                As[h * 8 + akk + 2][am] = ra[h].z;
                As[h * 8 + akk + 3][am] = ra[h].w;
            } else {
                *(float4*)&As[kr][c4] = ra[h];
            }
            *(float4*)&Bs[kr][c4] = rb[h];
        }
        __syncthreads();   // tiles visible

        // ---- compute 32 k-steps ----
#pragma unroll
        for (int k = 0; k < BK; k++) {
            float4 a0 = *(const float4*)&As[k][ty * 8];
            float4 a1 = *(const float4*)&As[k][ty * 8 + 4];
            float4 b0 = *(const float4*)&Bs[k][tx * 4];
            float4 b1 = *(const float4*)&Bs[k][64 + tx * 4];
            const float av[8] = {a0.x, a0.y, a0.z, a0.w, a1.x, a1.y, a1.z, a1.w};
            const float bv[8] = {b0.x, b0.y, b0.z, b0.w, b1.x, b1.y, b1.z, b1.w};
#pragma unroll
            for (int i = 0; i < 8; i++)
#pragma unroll
                for (int j = 0; j < 8; j++)
                    acc[i][j] = fmaf(av[i], bv[j], acc[i][j]);
        }
    }

    // ---- epilogue: rows m0+ty*8+i; col groups n0+tx*4 and n0+64+tx*4 ----
#pragma unroll
    for (int i = 0; i < 8; i++) {
        float* crow = Cp + (size_t)b * bsC + (size_t)(m0 + ty * 8 + i) * ldc + n0;
        *reinterpret_cast<float4*>(crow + tx * 4) =
            make_float4(acc[i][0], acc[i][1], acc[i][2], acc[i][3]);
        *reinterpret_cast<float4*>(crow + 64 + tx * 4) =
            make_float4(acc[i][4], acc[i][5], acc[i][6], acc[i][7]);
    }
}

// ---------------------------------------------------------------------------
// Launch: out = Q @ (K^T @ V). key_pe / hidden_size are dead inputs
// (attn_pos and the softmax are dead code in the reference).
// ---------------------------------------------------------------------------
extern "C" void kernel_launch(void* const* d_in, const int* in_sizes, int n_in,
                              void* d_out, int out_size)
{
    const float* q = (const float*)d_in[0];  // [B, M, H]
    const float* k = (const float*)d_in[1];  // [B, L, H]
    const float* v = (const float*)d_in[2];  // [B, L, H]
    float* out = (float*)d_out;              // [B, M, H]

    // 1) T[i][j] = sum_l K[l][i] V[l][j]   (A = K k-major, B = V k-major)
    {
        dim3 g1(HDIM / 128, HDIM / 128, BATCH);
        sgemm<0><<<g1, 256>>>(
            k, HDIM, (size_t)LDIM * HDIM,
            v, HDIM, (size_t)LDIM * HDIM,
            g_T, HDIM, (size_t)HDIM * HDIM,
            LDIM);
    }

    // 2) O[m][j] = sum_h Q[m][h] T[h][j]   (A = Q m-major, B = T k-major)
    {
        dim3 g2(HDIM / 128, MDIM / 128, BATCH);
        sgemm<1><<<g2, 256>>>(
            q, HDIM, (size_t)MDIM * HDIM,
            g_T, HDIM, (size_t)HDIM * HDIM,
            out, HDIM, (size_t)MDIM * HDIM,
            HDIM);
    }
}

// round 14
// speedup vs baseline: 9.6993x; 2.5987x over previous
#include <cuda_runtime.h>
#include <cstdint>

#define BATCH 8
#define MDIM  2048
#define LDIM  2048
#define HDIM  1024
#define BK    16
#define NTHREADS 256

// Scratch: T = K^T V, [B,H,H] fp32 (module-load allocated; allocs forbidden)
__device__ float g_T[(size_t)BATCH * HDIM * HDIM];

// ---------------------------------------------------------------------------
// Kernel 1: T[i][j] = sum_l K[l][i] * V[l][j]    (both operands k-major)
// 128x128 tile, BK=16, 256 threads, 8x8 microtile.
// Fragments: rows ty*8 (broadcast), cols tx*4 & 64+tx*4 (conflict-free).
// Inline LDG->STS, transient regs only (R8/R9: persistent/large load state
// hits the 128-reg cap and spills; cp.async measured pathological).
// ---------------------------------------------------------------------------
__global__ __launch_bounds__(NTHREADS, 2) void ktv_kernel(
    const float* __restrict__ Kp, const float* __restrict__ Vp)
{
    const int b = blockIdx.z;
    const float* A = Kp + (size_t)b * LDIM * HDIM;  // [L,H] rows l
    const float* B = Vp + (size_t)b * LDIM * HDIM;  // [L,H] rows l
    float* C = g_T + (size_t)b * HDIM * HDIM;       // [H,H]

    __shared__ float As[BK][128];
    __shared__ float Bs[BK][128];

    const int tid = threadIdx.x;
    const int ty = tid >> 4, tx = tid & 15;
    const int m0 = blockIdx.y * 128, n0 = blockIdx.x * 128;

    float acc[8][8];
#pragma unroll
    for (int i = 0; i < 8; i++)
#pragma unroll
        for (int j = 0; j < 8; j++) acc[i][j] = 0.0f;

    for (int l0 = 0; l0 < LDIM; l0 += BK) {
        // 2 float4 per thread per matrix (transient)
        float4 ra0, ra1, rb0, rb1;
        {
            const int kr0 = tid >> 5, c40 = (tid & 31) << 2;
            const int kr1 = kr0 + 8;
            ra0 = *(const float4*)(A + (size_t)(l0 + kr0) * HDIM + m0 + c40);
            ra1 = *(const float4*)(A + (size_t)(l0 + kr1) * HDIM + m0 + c40);
            rb0 = *(const float4*)(B + (size_t)(l0 + kr0) * HDIM + n0 + c40);
            rb1 = *(const float4*)(B + (size_t)(l0 + kr1) * HDIM + n0 + c40);
            __syncthreads();
            *(float4*)&As[kr0][c40] = ra0;
            *(float4*)&As[kr1][c40] = ra1;
            *(float4*)&Bs[kr0][c40] = rb0;
            *(float4*)&Bs[kr1][c40] = rb1;
        }
        __syncthreads();

#pragma unroll
        for (int k = 0; k < BK; k++) {
            float4 a0 = *(const float4*)&As[k][ty * 8];
            float4 a1 = *(const float4*)&As[k][ty * 8 + 4];
            float4 b0 = *(const float4*)&Bs[k][tx * 4];
            float4 b1 = *(const float4*)&Bs[k][64 + tx * 4];
            const float av[8] = {a0.x, a0.y, a0.z, a0.w, a1.x, a1.y, a1.z, a1.w};
            const float bv[8] = {b0.x, b0.y, b0.z, b0.w, b1.x, b1.y, b1.z, b1.w};
#pragma unroll
            for (int i = 0; i < 8; i++)
#pragma unroll
                for (int j = 0; j < 8; j++)
                    acc[i][j] = fmaf(av[i], bv[j], acc[i][j]);
        }
    }

#pragma unroll
    for (int i = 0; i < 8; i++) {
        float* crow = C + (size_t)(m0 + ty * 8 + i) * HDIM + n0;
        *reinterpret_cast<float4*>(crow + tx * 4) =
            make_float4(acc[i][0], acc[i][1], acc[i][2], acc[i][3]);
        *reinterpret_cast<float4*>(crow + 64 + tx * 4) =
            make_float4(acc[i][4], acc[i][5], acc[i][6], acc[i][7]);
    }
}

// ---------------------------------------------------------------------------
// Kernel 2: O[m][j] = sum_h Q[m][h] * T[h][j]
// A = Q [M,H] m-major -> transpose-on-STS; B = T [H,H] k-major direct.
// ---------------------------------------------------------------------------
__global__ __launch_bounds__(NTHREADS, 2) void qt_kernel(
    const float* __restrict__ Qp, float* __restrict__ Op)
{
    const int b = blockIdx.z;
    const float* A = Qp + (size_t)b * MDIM * HDIM;  // [M,H] rows m
    const float* B = g_T + (size_t)b * HDIM * HDIM; // [H,H] rows h
    float* C = Op + (size_t)b * MDIM * HDIM;        // [M,H]

    __shared__ float As[BK][128];
    __shared__ float Bs[BK][128];

    const int tid = threadIdx.x;
    const int ty = tid >> 4, tx = tid & 15;
    const int m0 = blockIdx.y * 128, n0 = blockIdx.x * 128;

    float acc[8][8];
#pragma unroll
    for (int i = 0; i < 8; i++)
#pragma unroll
        for (int j = 0; j < 8; j++) acc[i][j] = 0.0f;

    // A tile: 128 rows x 16 k = 512 float4; 2 per thread (rows tid>>2, +64)
    const int am = tid >> 2;             // 0..63
    const int akk = (tid & 3) << 2;      // 0,4,8,12
    // B tile: 16 rows x 128 = 512 float4; rows tid>>5 and +8
    const int bk0 = tid >> 5, bc0 = (tid & 31) << 2;

    for (int h0 = 0; h0 < HDIM; h0 += BK) {
        float4 ra0, ra1, rb0, rb1;
        ra0 = *(const float4*)(A + (size_t)(m0 + am) * HDIM + h0 + akk);
        ra1 = *(const float4*)(A + (size_t)(m0 + 64 + am) * HDIM + h0 + akk);
        rb0 = *(const float4*)(B + (size_t)(h0 + bk0) * HDIM + n0 + bc0);
        rb1 = *(const float4*)(B + (size_t)(h0 + bk0 + 8) * HDIM + n0 + bc0);
        __syncthreads();
        As[akk + 0][am] = ra0.x;
        As[akk + 1][am] = ra0.y;
        As[akk + 2][am] = ra0.z;
        As[akk + 3][am] = ra0.w;
        As[akk + 0][64 + am] = ra1.x;
        As[akk + 1][64 + am] = ra1.y;
        As[akk + 2][64 + am] = ra1.z;
        As[akk + 3][64 + am] = ra1.w;
        *(float4*)&Bs[bk0][bc0] = rb0;
        *(float4*)&Bs[bk0 + 8][bc0] = rb1;
        __syncthreads();

#pragma unroll
        for (int k = 0; k < BK; k++) {
            float4 a0 = *(const float4*)&As[k][ty * 8];
            float4 a1 = *(const float4*)&As[k][ty * 8 + 4];
            float4 b0 = *(const float4*)&Bs[k][tx * 4];
            float4 b1 = *(const float4*)&Bs[k][64 + tx * 4];
            const float av[8] = {a0.x, a0.y, a0.z, a0.w, a1.x, a1.y, a1.z, a1.w};
            const float bv[8] = {b0.x, b0.y, b0.z, b0.w, b1.x, b1.y, b1.z, b1.w};
#pragma unroll
            for (int i = 0; i < 8; i++)
#pragma unroll
                for (int j = 0; j < 8; j++)
                    acc[i][j] = fmaf(av[i], bv[j], acc[i][j]);
        }
    }

#pragma unroll
    for (int i = 0; i < 8; i++) {
        float* crow = C + (size_t)(m0 + ty * 8 + i) * HDIM + n0;
        *reinterpret_cast<float4*>(crow + tx * 4) =
            make_float4(acc[i][0], acc[i][1], acc[i][2], acc[i][3]);
        *reinterpret_cast<float4*>(crow + 64 + tx * 4) =
            make_float4(acc[i][4], acc[i][5], acc[i][6], acc[i][7]);
    }
}

// ---------------------------------------------------------------------------
// Launch: out = Q @ (K^T @ V). key_pe / hidden_size are dead inputs
// (attn_pos and the softmax are dead code in the reference).
// ---------------------------------------------------------------------------
extern "C" void kernel_launch(void* const* d_in, const int* in_sizes, int n_in,
                              void* d_out, int out_size)
{
    const float* q = (const float*)d_in[0];  // [B, M, H]
    const float* k = (const float*)d_in[1];  // [B, L, H]
    const float* v = (const float*)d_in[2];  // [B, L, H]
    float* out = (float*)d_out;              // [B, M, H]

    dim3 g1(HDIM / 128, HDIM / 128, BATCH);
    ktv_kernel<<<g1, NTHREADS>>>(k, v);

    dim3 g2(HDIM / 128, MDIM / 128, BATCH);
    qt_kernel<<<g2, NTHREADS>>>(q, out);
}